// round 7
// baseline (speedup 1.0000x reference)
#include <cuda_runtime.h>
#include <cuda_fp16.h>
#include <cstdint>

// Problem constants
#define B_    256
#define N_    128
#define EB_   5
#define NA_   64
#define DIM_  512
#define NIT_  3
#define MROWS (B_ * N_)

// ---------------------------------------------------------------------------
// Static device scratch.  All GEMM operands live as PRE-SPLIT half hi/lo pairs
// (3xFP16 split: x ≈ hi + lo, |lo| <= 2^-11 |x|).  fp32 hT kept only for the
// finalize reduction.  t never exists in fp32.
// Scaling convention: hh/hl store h/64, th/tl store t/64 (fp16 range safety);
// weights / adjacency / node stored unscaled.
// ---------------------------------------------------------------------------
__device__ __align__(128) float  g_hT[B_ * DIM_ * N_];                  // [B][512][128]
__device__ __align__(128) __half g_wh[NIT_ * DIM_ * DIM_ + DIM_ * NA_]; // transposed weights
__device__ __align__(128) __half g_wl[NIT_ * DIM_ * DIM_ + DIM_ * NA_];
__device__ __align__(128) __half g_ah[B_ * N_ * N_];                    // Σedges + I
__device__ __align__(128) __half g_al[B_ * N_ * N_];
__device__ __align__(128) __half g_nh[MROWS * NA_];                     // node
__device__ __align__(128) __half g_nl[MROWS * NA_];
__device__ __align__(128) __half g_th[B_ * N_ * DIM_];                  // t/64
__device__ __align__(128) __half g_tl[B_ * N_ * DIM_];
__device__ __align__(128) __half g_hh[B_ * DIM_ * N_];                  // h/64
__device__ __align__(128) __half g_hl[B_ * DIM_ * N_];

// ---------------------------------------------------------------------------
// helpers
// ---------------------------------------------------------------------------
__device__ __forceinline__ void split2(float a0, float a1, __half2& hi, __half2& lo) {
    hi = __floats2half2_rn(a0, a1);
    float2 f = __half22float2(hi);
    lo = __floats2half2_rn(a0 - f.x, a1 - f.y);
}

__device__ __forceinline__ uint32_t smem_u32(const void* p) {
    uint32_t a;
    asm("{ .reg .u64 t; cvta.to.shared.u64 t, %1; cvt.u32.u64 %0, t; }" : "=r"(a) : "l"(p));
    return a;
}

__device__ __forceinline__ void cpasync16(uint32_t s, const void* g) {
    asm volatile("cp.async.cg.shared.global [%0], [%1], 16;" :: "r"(s), "l"(g));
}
#define CP_COMMIT() asm volatile("cp.async.commit_group;" ::: "memory")
#define CP_WAIT0()  asm volatile("cp.async.wait_group 0;" ::: "memory")

#define LDSM4(r, addr) \
    asm volatile("ldmatrix.sync.aligned.m8n8.x4.shared.b16 {%0,%1,%2,%3}, [%4];" \
        : "=r"((r)[0]), "=r"((r)[1]), "=r"((r)[2]), "=r"((r)[3]) : "r"(addr))

__device__ __forceinline__ void mma16816(float* c, const uint32_t* a,
                                         uint32_t b0, uint32_t b1) {
    asm volatile(
        "mma.sync.aligned.m16n8k16.row.col.f32.f16.f16.f32 "
        "{%0,%1,%2,%3}, {%4,%5,%6,%7}, {%8,%9}, {%0,%1,%2,%3};"
        : "+f"(c[0]), "+f"(c[1]), "+f"(c[2]), "+f"(c[3])
        : "r"(a[0]), "r"(a[1]), "r"(a[2]), "r"(a[3]), "r"(b0), "r"(b1));
}

// ---------------------------------------------------------------------------
// Prep kernels (run once per launch; all tiny except asum which streams adj)
// ---------------------------------------------------------------------------
__global__ void asum_split_kernel(const float* __restrict__ adj,
                                  __half* __restrict__ ah, __half* __restrict__ al) {
    int i = (blockIdx.x * 256 + threadIdx.x) * 2;          // exact grid
    const float* p = adj + (long long)i * EB_;
    float s0 = p[1] + p[2] + p[3] + p[4];
    float s1 = p[6] + p[7] + p[8] + p[9];
    int nm0 = i & (N_ * N_ - 1);
    int nm1 = (i + 1) & (N_ * N_ - 1);
    if ((nm0 >> 7) == (nm0 & 127)) s0 += 1.0f;             // fold residual (+I)
    if ((nm1 >> 7) == (nm1 & 127)) s1 += 1.0f;
    __half2 h, l; split2(s0, s1, h, l);
    ((__half2*)ah)[i >> 1] = h;
    ((__half2*)al)[i >> 1] = l;
}

// transpose + split:  dst[c][r] = src[r][c]   (dst K-major for GEMM A operand)
__global__ void tsplit_kernel(const float* __restrict__ src,
                              __half* __restrict__ dh, __half* __restrict__ dl,
                              int R, int C) {
    int idx = blockIdx.x * 256 + threadIdx.x;              // over C * R/2
    if (idx >= C * (R >> 1)) return;
    int c = idx / (R >> 1), rp = idx % (R >> 1);
    float v0 = src[(2 * rp)     * C + c];
    float v1 = src[(2 * rp + 1) * C + c];
    __half2 h, l; split2(v0, v1, h, l);
    ((__half2*)dh)[c * (R >> 1) + rp] = h;
    ((__half2*)dl)[c * (R >> 1) + rp] = l;
}

__global__ void nsplit_kernel(const float* __restrict__ node,
                              __half* __restrict__ nh, __half* __restrict__ nl) {
    int i = blockIdx.x * 256 + threadIdx.x;                // over MROWS*NA/2
    float2 v = ((const float2*)node)[i];
    __half2 h, l; split2(v.x, v.y, h, l);
    ((__half2*)nh)[i] = h;
    ((__half2*)nl)[i] = l;
}

// ---------------------------------------------------------------------------
// Pure-half 3-term tensor GEMM:   D[128,128] tile of  A[M,K] @ B[N,K]^T
//   acc = Ah*Bh + Al*Bh + Ah*Bl   (fp32 accum; inputs pre-split)
//   v   = acc*outScale + bias, relu optional
//   Df (fp32, nullable) <- v;  Dh/Dl <- split(v * halfScale)
// Smem: [2 buf][Ah,Al,Bh,Bl] tiles of [128 rows][32 halves], row stride 80B
//   (stride 20 u32 -> ldmatrix 8-row groups cover all 32 banks, conflict-free;
//    80B is 16B-aligned for ldmatrix/cp.async).
// K-chunk 32, cp.async double buffer, 1 syncthreads per chunk.
// ---------------------------------------------------------------------------
#define RSB     80                      // row stride bytes
#define TILE_B  (128 * RSB)             // 10240 B
#define OFF_AH  0
#define OFF_AL  (TILE_B)
#define OFF_BH  (2 * TILE_B)
#define OFF_BL  (3 * TILE_B)
#define BUF_B   (4 * TILE_B)            // 40960 B
#define SMEM_BYTES (2 * BUF_B)          // 81920 B

__global__ __launch_bounds__(256, 2)
void tgemm_h(const __half* __restrict__ Ah, const __half* __restrict__ Al, long long aBS,
             const __half* __restrict__ Bh, const __half* __restrict__ Bl, long long bBS,
             float* __restrict__ Df, __half* __restrict__ Dh, __half* __restrict__ Dl,
             long long dBS, const float* __restrict__ bias,
             int K, int Nglob, int ntiles, int relu,
             float outScale, float halfScale)
{
    extern __shared__ uint32_t sdyn[];
    const uint32_t sb = smem_u32(sdyn);

    const int tid  = threadIdx.x;
    const int lane = tid & 31;
    const int warp = tid >> 5;
    const int mtb  = blockIdx.x / ntiles;
    const int ntb  = blockIdx.x % ntiles;
    const int wm   = (warp >> 2) * 64;
    const int wn   = (warp & 3) * 32;

    // loader mapping: row = tid>>1, 32B half-row selected by tid&1
    const int lr = tid >> 1;
    const int hs = tid & 1;
    const long long gofs = (long long)lr * K + hs * 16;
    const __half* gAh = Ah + aBS * blockIdx.y + (long long)mtb * 128 * K + gofs;
    const __half* gAl = Al + aBS * blockIdx.y + (long long)mtb * 128 * K + gofs;
    const __half* gBh = Bh + bBS * blockIdx.y + (long long)ntb * 128 * K + gofs;
    const __half* gBl = Bl + bBS * blockIdx.y + (long long)ntb * 128 * K + gofs;
    const uint32_t swr = sb + lr * RSB + hs * 32;

    float acc[4][4][4];
    #pragma unroll
    for (int i = 0; i < 4; i++)
        #pragma unroll
        for (int j = 0; j < 4; j++)
            #pragma unroll
            for (int q = 0; q < 4; q++) acc[i][j][q] = 0.0f;

    // fragment addressing constants
    const int frow  = lane & 15;
    const int fkoff = (lane >> 4) * 16;
    uint32_t aRow[4], bRow[2];
    #pragma unroll
    for (int mt = 0; mt < 4; mt++) aRow[mt] = (uint32_t)(wm + mt * 16 + frow) * RSB;
    #pragma unroll
    for (int p = 0; p < 2; p++)    bRow[p]  = (uint32_t)(wn + p * 16 + frow) * RSB;

    const int C = K >> 5;   // K-chunks of 32

    // prologue: chunk 0 -> buf 0
    {
        const uint32_t o = swr;
        cpasync16(o + OFF_AH,      gAh);     cpasync16(o + OFF_AH + 16, gAh + 8);
        cpasync16(o + OFF_AL,      gAl);     cpasync16(o + OFF_AL + 16, gAl + 8);
        cpasync16(o + OFF_BH,      gBh);     cpasync16(o + OFF_BH + 16, gBh + 8);
        cpasync16(o + OFF_BL,      gBl);     cpasync16(o + OFF_BL + 16, gBl + 8);
        CP_COMMIT();
    }
    CP_WAIT0();
    __syncthreads();

    int buf = 0;
    for (int c = 0; c < C; c++) {
        // issue chunk c+1 into the other buffer
        if (c + 1 < C) {
            const uint32_t o = swr + (buf ^ 1) * BUF_B;
            const int g = (c + 1) * 32;
            cpasync16(o + OFF_AH,      gAh + g);  cpasync16(o + OFF_AH + 16, gAh + g + 8);
            cpasync16(o + OFF_AL,      gAl + g);  cpasync16(o + OFF_AL + 16, gAl + g + 8);
            cpasync16(o + OFF_BH,      gBh + g);  cpasync16(o + OFF_BH + 16, gBh + g + 8);
            cpasync16(o + OFF_BL,      gBl + g);  cpasync16(o + OFF_BL + 16, gBl + g + 8);
            CP_COMMIT();
        }

        const uint32_t bb = sb + buf * BUF_B;
        #pragma unroll
        for (int s = 0; s < 2; s++) {                 // two k16 slices
            const uint32_t kb = bb + s * 32 + fkoff;
            uint32_t Af[4][4], Bf[2][4];
            #pragma unroll
            for (int mt = 0; mt < 4; mt++) LDSM4(Af[mt], kb + OFF_AH + aRow[mt]);
            #pragma unroll
            for (int p = 0; p < 2; p++)    LDSM4(Bf[p],  kb + OFF_BH + bRow[p]);
            // term 1: Ah * Bh
            #pragma unroll
            for (int mt = 0; mt < 4; mt++)
                #pragma unroll
                for (int p = 0; p < 2; p++) {
                    mma16816(acc[mt][2 * p],     Af[mt], Bf[p][0], Bf[p][2]);
                    mma16816(acc[mt][2 * p + 1], Af[mt], Bf[p][1], Bf[p][3]);
                }
            // term 2: Al * Bh
            uint32_t Alf[4][4];
            #pragma unroll
            for (int mt = 0; mt < 4; mt++) LDSM4(Alf[mt], kb + OFF_AL + aRow[mt]);
            #pragma unroll
            for (int mt = 0; mt < 4; mt++)
                #pragma unroll
                for (int p = 0; p < 2; p++) {
                    mma16816(acc[mt][2 * p],     Alf[mt], Bf[p][0], Bf[p][2]);
                    mma16816(acc[mt][2 * p + 1], Alf[mt], Bf[p][1], Bf[p][3]);
                }
            // term 3: Ah * Bl  (Bl overwrites Bh regs)
            #pragma unroll
            for (int p = 0; p < 2; p++)    LDSM4(Bf[p],  kb + OFF_BL + bRow[p]);
            #pragma unroll
            for (int mt = 0; mt < 4; mt++)
                #pragma unroll
                for (int p = 0; p < 2; p++) {
                    mma16816(acc[mt][2 * p],     Af[mt], Bf[p][0], Bf[p][2]);
                    mma16816(acc[mt][2 * p + 1], Af[mt], Bf[p][1], Bf[p][3]);
                }
        }

        if (c + 1 < C) CP_WAIT0();
        __syncthreads();
        buf ^= 1;
    }

    // --- epilogue ---
    // C frag: c0:(r,cc) c1:(r,cc+1) c2:(r+8,cc) c3:(r+8,cc+1);
    //   r = wm + mt*16 + lane/4, cc = wn + nt*8 + 2*(lane&3)
    const long long dbase = dBS * blockIdx.y + (long long)mtb * 128 * Nglob + ntb * 128;
    float*   Dfp = Df ? Df + dbase : nullptr;
    __half2* Dhp = (__half2*)Dh + (dbase >> 1);
    __half2* Dlp = (__half2*)Dl + (dbase >> 1);

    #pragma unroll
    for (int mt = 0; mt < 4; mt++) {
        const int rr0 = wm + mt * 16 + (lane >> 2);
        const int rr1 = rr0 + 8;
        const float bv0 = bias ? bias[mtb * 128 + rr0] : 0.0f;
        const float bv1 = bias ? bias[mtb * 128 + rr1] : 0.0f;
        #pragma unroll
        for (int nt = 0; nt < 4; nt++) {
            const int cc = wn + nt * 8 + 2 * (lane & 3);
            float v0 = acc[mt][nt][0] * outScale + bv0;
            float v1 = acc[mt][nt][1] * outScale + bv0;
            float v2 = acc[mt][nt][2] * outScale + bv1;
            float v3 = acc[mt][nt][3] * outScale + bv1;
            if (relu) {
                v0 = fmaxf(v0, 0.0f); v1 = fmaxf(v1, 0.0f);
                v2 = fmaxf(v2, 0.0f); v3 = fmaxf(v3, 0.0f);
            }
            const long long i0 = (long long)rr0 * Nglob + cc;
            const long long i1 = (long long)rr1 * Nglob + cc;
            if (Dfp) {
                *(float2*)(Dfp + i0) = make_float2(v0, v1);
                *(float2*)(Dfp + i1) = make_float2(v2, v3);
            }
            __half2 h, l;
            split2(v0 * halfScale, v1 * halfScale, h, l);
            Dhp[i0 >> 1] = h; Dlp[i0 >> 1] = l;
            split2(v2 * halfScale, v3 * halfScale, h, l);
            Dhp[i1 >> 1] = h; Dlp[i1 >> 1] = l;
        }
    }
}

// ---------------------------------------------------------------------------
// finalize: graph_repr[b] = mean_n hT[b][d][n];  logit = repr @ W_out + b_out
// out = [ logit(256) | graph_repr(256*512) ]
// ---------------------------------------------------------------------------
__global__ void finalize_kernel(const float* __restrict__ hT,
                                const float* __restrict__ W_out,
                                const float* __restrict__ b_out,
                                float* __restrict__ out)
{
    const int b = blockIdx.x, tid = threadIdx.x;
    const float* base = hT + (long long)b * DIM_ * N_;
    const float4* r0 = (const float4*)(base + (long long)tid * N_);
    const float4* r1 = (const float4*)(base + (long long)(tid + 256) * N_);
    float s0 = 0.0f, s1 = 0.0f;
    #pragma unroll 8
    for (int j = 0; j < 32; j++) {
        float4 a = r0[j]; s0 += (a.x + a.y) + (a.z + a.w);
        float4 c = r1[j]; s1 += (c.x + c.y) + (c.z + c.w);
    }
    const float g0 = s0 * (1.0f / (float)N_);
    const float g1 = s1 * (1.0f / (float)N_);
    out[B_ + b * DIM_ + tid]       = g0;
    out[B_ + b * DIM_ + tid + 256] = g1;

    __shared__ float red[256];
    red[tid] = g0 * W_out[tid] + g1 * W_out[tid + 256];
    __syncthreads();
    for (int s = 128; s > 0; s >>= 1) {
        if (tid < s) red[tid] += red[tid + s];
        __syncthreads();
    }
    if (tid == 0) out[b] = red[0] + b_out[0];
}

// ---------------------------------------------------------------------------
// launch
// ---------------------------------------------------------------------------
extern "C" void kernel_launch(void* const* d_in, const int* in_sizes, int n_in,
                              void* d_out, int out_size)
{
    const float* adj      = (const float*)d_in[0];
    // d_in[1] = hidden (unused by forward)
    const float* node     = (const float*)d_in[2];
    const float* W_embed  = (const float*)d_in[3];
    const float* b_embed  = (const float*)d_in[4];
    const float* W_layers = (const float*)d_in[5];
    const float* b_layers = (const float*)d_in[6];
    const float* W_out    = (const float*)d_in[7];
    const float* b_out    = (const float*)d_in[8];
    float* out = (float*)d_out;

    float *hT;
    __half *wh, *wl, *ah, *al, *nh, *nl, *th, *tl, *hh, *hl;
    cudaGetSymbolAddress((void**)&hT, g_hT);
    cudaGetSymbolAddress((void**)&wh, g_wh);
    cudaGetSymbolAddress((void**)&wl, g_wl);
    cudaGetSymbolAddress((void**)&ah, g_ah);
    cudaGetSymbolAddress((void**)&al, g_al);
    cudaGetSymbolAddress((void**)&nh, g_nh);
    cudaGetSymbolAddress((void**)&nl, g_nl);
    cudaGetSymbolAddress((void**)&th, g_th);
    cudaGetSymbolAddress((void**)&tl, g_tl);
    cudaGetSymbolAddress((void**)&hh, g_hh);
    cudaGetSymbolAddress((void**)&hl, g_hl);

    cudaFuncSetAttribute(tgemm_h, cudaFuncAttributeMaxDynamicSharedMemorySize,
                         SMEM_BYTES);

    // ---- prep: fold + split all static operands ----
    asum_split_kernel<<<(B_ * N_ * N_) / 512, 256>>>(adj, ah, al);
    for (int i = 0; i < NIT_; i++)
        tsplit_kernel<<<(DIM_ * (DIM_ / 2) + 255) / 256, 256>>>(
            W_layers + (long long)i * DIM_ * DIM_,
            wh + (long long)i * DIM_ * DIM_, wl + (long long)i * DIM_ * DIM_,
            DIM_, DIM_);
    tsplit_kernel<<<(DIM_ * (NA_ / 2) + 255) / 256, 256>>>(
        W_embed, wh + (long long)NIT_ * DIM_ * DIM_, wl + (long long)NIT_ * DIM_ * DIM_,
        NA_, DIM_);
    nsplit_kernel<<<(MROWS * NA_) / 512, 256>>>(node, nh, nl);

    dim3 grid(4, B_);
    const float INV64 = 1.0f / 64.0f;

    // embed: hT[b][512][128] = WembT @ node[b]^T + b_embed   (K=64)
    //   fp32 -> hT; halves -> hh/hl (= h/64)
    tgemm_h<<<grid, 256, SMEM_BYTES>>>(
        wh + (long long)NIT_ * DIM_ * DIM_, wl + (long long)NIT_ * DIM_ * DIM_, 0LL,
        nh, nl, (long long)N_ * NA_,
        hT, hh, hl, (long long)DIM_ * N_,
        b_embed, NA_, N_, /*ntiles=*/1, /*relu=*/0,
        /*outScale=*/1.0f, /*halfScale=*/INV64);

    for (int i = 0; i < NIT_; i++) {
        // agg: t/64 = asumI @ (h/64)   (K=128)  -> th/tl only (no fp32)
        tgemm_h<<<grid, 256, SMEM_BYTES>>>(
            ah, al, (long long)N_ * N_,
            hh, hl, (long long)DIM_ * N_,
            nullptr, th, tl, (long long)N_ * DIM_,
            nullptr, N_, DIM_, /*ntiles=*/4, /*relu=*/0,
            /*outScale=*/1.0f, /*halfScale=*/1.0f);
        // layer: h = relu(64 * (WT @ t/64) + b)   (K=512)
        //   fp32 -> hT; halves -> hh/hl (= h/64)
        tgemm_h<<<grid, 256, SMEM_BYTES>>>(
            wh + (long long)i * DIM_ * DIM_, wl + (long long)i * DIM_ * DIM_, 0LL,
            th, tl, (long long)N_ * DIM_,
            hT, hh, hl, (long long)DIM_ * N_,
            b_layers + i * DIM_, DIM_, N_, /*ntiles=*/1, /*relu=*/1,
            /*outScale=*/64.0f, /*halfScale=*/INV64);
    }

    finalize_kernel<<<B_, 256>>>(hT, W_out, b_out, out);
}

// round 8
// speedup vs baseline: 1.0194x; 1.0194x over previous
#include <cuda_runtime.h>
#include <cuda_fp16.h>
#include <cstdint>

// Problem constants
#define B_    256
#define N_    128
#define EB_   5
#define NA_   64
#define DIM_  512
#define NIT_  3
#define MROWS (B_ * N_)

// Scratch (static device globals)
__device__ __align__(128) float g_asumI[B_ * N_ * N_];   // [B][128][128]  Σedges + I
__device__ __align__(128) float g_hT[B_ * DIM_ * N_];    // [B][512][128]  hidden (transposed)
__device__ __align__(128) float g_t [B_ * N_ * DIM_];    // [B][128][512]  (I+A)h
__device__ __align__(128) float g_wT[NIT_ * DIM_ * DIM_ + DIM_ * NA_]; // wT (+embed at end)

// ---------------------------------------------------------------------------
// helpers
// ---------------------------------------------------------------------------
__device__ __forceinline__ uint32_t pack2(__half2 v) {
    return *reinterpret_cast<uint32_t*>(&v);
}
__device__ __forceinline__ void split2u(float a0, float a1, uint32_t& hi, uint32_t& lo) {
    __half2 h = __floats2half2_rn(a0, a1);
    float2  f = __half22float2(h);
    __half2 l = __floats2half2_rn(a0 - f.x, a1 - f.y);
    hi = pack2(h); lo = pack2(l);
}
__device__ __forceinline__ void mma16816(float* c, const uint32_t* a,
                                         uint32_t b0, uint32_t b1) {
    asm volatile(
        "mma.sync.aligned.m16n8k16.row.col.f32.f16.f16.f32 "
        "{%0,%1,%2,%3}, {%4,%5,%6,%7}, {%8,%9}, {%0,%1,%2,%3};"
        : "+f"(c[0]), "+f"(c[1]), "+f"(c[2]), "+f"(c[3])
        : "r"(a[0]), "r"(a[1]), "r"(a[2]), "r"(a[3]), "r"(b0), "r"(b1));
}

// ---------------------------------------------------------------------------
// Prep kernels
// ---------------------------------------------------------------------------
// asum: 4 outputs per thread via 5 float4 loads; folds +I (residual)
__global__ void asum_kernel(const float* __restrict__ adj, float* __restrict__ asumI) {
    int g = blockIdx.x * 256 + threadIdx.x;            // over B*N*N/4, exact
    const float4* p = (const float4*)adj + (long long)g * 5;
    float4 f0 = p[0], f1 = p[1], f2 = p[2], f3 = p[3], f4 = p[4];
    float4 o;
    o.x = (f0.y + f0.z) + (f0.w + f1.x);   // f[1..4]
    o.y = (f1.z + f1.w) + (f2.x + f2.y);   // f[6..9]
    o.z = (f2.w + f3.x) + (f3.y + f3.z);   // f[11..14]
    o.w = (f4.x + f4.y) + (f4.z + f4.w);   // f[16..19]
    int i = g * 4;
    #pragma unroll
    for (int j = 0; j < 4; j++) {
        int nm = (i + j) & (N_ * N_ - 1);
        if ((nm >> 7) == (nm & 127)) (&o.x)[j] += 1.0f;
    }
    ((float4*)asumI)[g] = o;
}

// fused transpose of all weights into wT (layers then embed), K-major for GEMM A
__global__ void wtrans_kernel(const float* __restrict__ W_layers,
                              const float* __restrict__ W_embed,
                              float* __restrict__ wT) {
    int i = blockIdx.x * 256 + threadIdx.x;            // exact grid 3200*256
    const int LSZ = DIM_ * DIM_;
    if (i < NIT_ * LSZ) {
        int l = i / LSZ, j = i % LSZ;
        int c = j / DIM_, r = j % DIM_;                // wT[l][c][r] = W[l][r][c]
        wT[i] = W_layers[l * LSZ + r * DIM_ + c];
    } else {
        int j = i - NIT_ * LSZ;                        // j < DIM_*NA_
        int c = j / NA_, r = j % NA_;                  // wT[c][r] = W_embed[r][c]
        wT[i] = W_embed[r * DIM_ + c];
    }
}

// ---------------------------------------------------------------------------
// 3xFP16-split tensor GEMM, 512 threads (16 warps, 32x32 warp tiles):
//   D[128,128] tile of A[M,K] @ B[N,K]^T, both K-major fp32 inputs.
//   acc = Ah*Bh + Ah*Bl + Al*Bh (fp32 accum); B pre-scaled by bScale at split,
//   epilogue v = acc*outScale + bias, optional relu.
// Smem: [2 buf][Ah,Al,Bh,Bl][k2=8][row 0..127] u32(half2), LDT=136
//   -> fragment LDS conflict-free.  1 syncthreads per K=16 chunk,
//   register-staged global prefetch overlaps compute.
// ---------------------------------------------------------------------------
#define LDT 136

__global__ __launch_bounds__(512, 1)
void tgemm(const float* __restrict__ A, long long aBS,
           const float* __restrict__ Bm, long long bBS,
           float* __restrict__ D, long long dBS,
           const float* __restrict__ bias,
           int K, int Nglob, int ntiles, int relu,
           float bScale, float outScale)
{
    __shared__ uint32_t S[2][4][8][LDT];   // 34816 B

    const int tid  = threadIdx.x;
    const int lane = tid & 31;
    const int warp = tid >> 5;             // 0..15
    const int mtb  = blockIdx.x / ntiles;
    const int ntb  = blockIdx.x % ntiles;
    const int wm   = (warp >> 2) * 32;     // 0,32,64,96
    const int wn   = (warp & 3) * 32;      // 0,32,64,96

    const float* Ap = A  + aBS * blockIdx.y + (long long)mtb * 128 * K;
    const float* Bp = Bm + bBS * blockIdx.y + (long long)ntb * 128 * K;

    // loader: row = tid>>2 (0..127), k2 base = (tid&3)*2 -> one float4 per operand
    const int lr  = tid >> 2;
    const int k2b = (tid & 3) * 2;
    const float* ag = Ap + (long long)lr * K + k2b * 2;
    const float* bg = Bp + (long long)lr * K + k2b * 2;

    float acc[2][4][4];
    #pragma unroll
    for (int i = 0; i < 2; i++)
        #pragma unroll
        for (int j = 0; j < 4; j++)
            #pragma unroll
            for (int q = 0; q < 4; q++) acc[i][j][q] = 0.0f;

    const int fr = lane >> 2;              // 0..7
    const int fq = lane & 3;               // k2 quad

    float4 aS = *(const float4*)ag;
    float4 bS = *(const float4*)bg;

    const int C = K >> 4;
    int buf = 0;

    for (int c = 0; c < C; c++) {
        // split + store chunk c
        {
            uint32_t h, l;
            split2u(aS.x, aS.y, h, l);
            S[buf][0][k2b][lr]     = h;  S[buf][1][k2b][lr]     = l;
            split2u(aS.z, aS.w, h, l);
            S[buf][0][k2b + 1][lr] = h;  S[buf][1][k2b + 1][lr] = l;
            split2u(bS.x * bScale, bS.y * bScale, h, l);
            S[buf][2][k2b][lr]     = h;  S[buf][3][k2b][lr]     = l;
            split2u(bS.z * bScale, bS.w * bScale, h, l);
            S[buf][2][k2b + 1][lr] = h;  S[buf][3][k2b + 1][lr] = l;
        }
        __syncthreads();

        // prefetch chunk c+1 (overlaps with compute)
        if (c + 1 < C) {
            aS = *(const float4*)(ag + (c + 1) * 16);
            bS = *(const float4*)(bg + (c + 1) * 16);
        }

        const uint32_t (*SAh)[LDT] = S[buf][0];
        const uint32_t (*SAl)[LDT] = S[buf][1];
        const uint32_t (*SBh)[LDT] = S[buf][2];
        const uint32_t (*SBl)[LDT] = S[buf][3];

        uint32_t af[2][4], bh[4][2], bl[4][2];
        #pragma unroll
        for (int mt = 0; mt < 2; mt++) {
            const int m0 = wm + mt * 16 + fr;
            af[mt][0] = SAh[fq][m0];
            af[mt][1] = SAh[fq][m0 + 8];
            af[mt][2] = SAh[fq + 4][m0];
            af[mt][3] = SAh[fq + 4][m0 + 8];
        }
        #pragma unroll
        for (int nt = 0; nt < 4; nt++) {
            const int n0 = wn + nt * 8 + fr;
            bh[nt][0] = SBh[fq][n0];
            bh[nt][1] = SBh[fq + 4][n0];
            bl[nt][0] = SBl[fq][n0];
            bl[nt][1] = SBl[fq + 4][n0];
        }
        // terms 1+3: Ah*Bh, Ah*Bl
        #pragma unroll
        for (int mt = 0; mt < 2; mt++)
            #pragma unroll
            for (int nt = 0; nt < 4; nt++) {
                mma16816(acc[mt][nt], af[mt], bh[nt][0], bh[nt][1]);
                mma16816(acc[mt][nt], af[mt], bl[nt][0], bl[nt][1]);
            }
        // term 2: Al*Bh
        #pragma unroll
        for (int mt = 0; mt < 2; mt++) {
            const int m0 = wm + mt * 16 + fr;
            af[mt][0] = SAl[fq][m0];
            af[mt][1] = SAl[fq][m0 + 8];
            af[mt][2] = SAl[fq + 4][m0];
            af[mt][3] = SAl[fq + 4][m0 + 8];
        }
        #pragma unroll
        for (int mt = 0; mt < 2; mt++)
            #pragma unroll
            for (int nt = 0; nt < 4; nt++)
                mma16816(acc[mt][nt], af[mt], bh[nt][0], bh[nt][1]);

        buf ^= 1;
    }

    // --- epilogue ---
    // frag map: c0:(r,cc) c1:(r,cc+1) c2:(r+8,cc) c3:(r+8,cc+1);
    //   r = wm + mt*16 + lane/4,  cc = wn + nt*8 + 2*(lane&3)
    float* Dp = D + dBS * blockIdx.y + (long long)mtb * 128 * Nglob + ntb * 128;
    #pragma unroll
    for (int mt = 0; mt < 2; mt++) {
        const int rr0 = wm + mt * 16 + (lane >> 2);
        const int rr1 = rr0 + 8;
        const float bv0 = bias ? bias[mtb * 128 + rr0] : 0.0f;
        const float bv1 = bias ? bias[mtb * 128 + rr1] : 0.0f;
        #pragma unroll
        for (int nt = 0; nt < 4; nt++) {
            const int cc = wn + nt * 8 + 2 * (lane & 3);
            float v0 = acc[mt][nt][0] * outScale + bv0;
            float v1 = acc[mt][nt][1] * outScale + bv0;
            float v2 = acc[mt][nt][2] * outScale + bv1;
            float v3 = acc[mt][nt][3] * outScale + bv1;
            if (relu) {
                v0 = fmaxf(v0, 0.0f); v1 = fmaxf(v1, 0.0f);
                v2 = fmaxf(v2, 0.0f); v3 = fmaxf(v3, 0.0f);
            }
            *(float2*)(Dp + (long long)rr0 * Nglob + cc) = make_float2(v0, v1);
            *(float2*)(Dp + (long long)rr1 * Nglob + cc) = make_float2(v2, v3);
        }
    }
}

// ---------------------------------------------------------------------------
// finalize: graph_repr[b] = mean_n hT[b][d][n];  logit = repr @ W_out + b_out
// out = [ logit(256) | graph_repr(256*512) ]
// ---------------------------------------------------------------------------
__global__ void finalize_kernel(const float* __restrict__ hT,
                                const float* __restrict__ W_out,
                                const float* __restrict__ b_out,
                                float* __restrict__ out)
{
    const int b = blockIdx.x, tid = threadIdx.x;
    const float* base = hT + (long long)b * DIM_ * N_;
    const float4* r0 = (const float4*)(base + (long long)tid * N_);
    const float4* r1 = (const float4*)(base + (long long)(tid + 256) * N_);
    float s0 = 0.0f, s1 = 0.0f;
    #pragma unroll 8
    for (int j = 0; j < 32; j++) {
        float4 a = r0[j]; s0 += (a.x + a.y) + (a.z + a.w);
        float4 c = r1[j]; s1 += (c.x + c.y) + (c.z + c.w);
    }
    const float g0 = s0 * (1.0f / (float)N_);
    const float g1 = s1 * (1.0f / (float)N_);
    out[B_ + b * DIM_ + tid]       = g0;
    out[B_ + b * DIM_ + tid + 256] = g1;

    __shared__ float red[256];
    red[tid] = g0 * W_out[tid] + g1 * W_out[tid + 256];
    __syncthreads();
    for (int s = 128; s > 0; s >>= 1) {
        if (tid < s) red[tid] += red[tid + s];
        __syncthreads();
    }
    if (tid == 0) out[b] = red[0] + b_out[0];
}

// ---------------------------------------------------------------------------
// launch
// ---------------------------------------------------------------------------
extern "C" void kernel_launch(void* const* d_in, const int* in_sizes, int n_in,
                              void* d_out, int out_size)
{
    const float* adj      = (const float*)d_in[0];
    // d_in[1] = hidden (unused by forward)
    const float* node     = (const float*)d_in[2];
    const float* W_embed  = (const float*)d_in[3];
    const float* b_embed  = (const float*)d_in[4];
    const float* W_layers = (const float*)d_in[5];
    const float* b_layers = (const float*)d_in[6];
    const float* W_out    = (const float*)d_in[7];
    const float* b_out    = (const float*)d_in[8];
    float* out = (float*)d_out;

    float *asumI, *hT, *t, *wT;
    cudaGetSymbolAddress((void**)&asumI, g_asumI);
    cudaGetSymbolAddress((void**)&hT,    g_hT);
    cudaGetSymbolAddress((void**)&t,     g_t);
    cudaGetSymbolAddress((void**)&wT,    g_wT);

    // prep (2 launches): folded adjacency (+I), fused weight transposes
    asum_kernel<<<(B_ * N_ * N_ / 4) / 256, 256>>>(adj, asumI);
    wtrans_kernel<<<(NIT_ * DIM_ * DIM_ + DIM_ * NA_) / 256, 256>>>(
        W_layers, W_embed, wT);

    dim3 grid(4, B_);
    const float S  = 1.0f / 64.0f;   // B-operand pre-scale (fp16 range safety)
    const float iS = 64.0f;

    // embed: hT[b][512][128] = WembT @ node[b]^T + b_embed   (K=64)
    tgemm<<<grid, 512>>>(
        wT + (long long)NIT_ * DIM_ * DIM_, 0LL,
        node, (long long)N_ * NA_,
        hT, (long long)DIM_ * N_,
        b_embed, NA_, N_, /*ntiles=*/1, /*relu=*/0, 1.0f, 1.0f);

    for (int i = 0; i < NIT_; i++) {
        // t[b][128x512] = asumI[b] @ hT[b]^T   (K=128)
        tgemm<<<grid, 512>>>(
            asumI, (long long)N_ * N_,
            hT, (long long)DIM_ * N_,
            t, (long long)N_ * DIM_,
            nullptr, N_, DIM_, /*ntiles=*/4, /*relu=*/0, S, iS);
        // hT[b][512x128] = relu(WT_i @ t[b]^T + b_i)   (K=512)
        tgemm<<<grid, 512>>>(
            wT + (long long)i * DIM_ * DIM_, 0LL,
            t, (long long)N_ * DIM_,
            hT, (long long)DIM_ * N_,
            b_layers + i * DIM_, DIM_, N_, /*ntiles=*/1, /*relu=*/1, S, iS);
    }

    finalize_kernel<<<B_, 256>>>(hT, W_out, b_out, out);
}

// round 9
// speedup vs baseline: 1.2392x; 1.2157x over previous
#include <cuda_runtime.h>
#include <cuda_fp16.h>
#include <cstdint>

// Problem constants
#define B_    256
#define N_    128
#define EB_   5
#define NA_   64
#define DIM_  512
#define NIT_  3
#define MROWS (B_ * N_)

// Scratch (static device globals)
__device__ __align__(128) float g_asumI[B_ * N_ * N_];   // [B][128][128]  Σedges + I
__device__ __align__(128) float g_hT[B_ * DIM_ * N_];    // [B][512][128]  hidden (transposed)
__device__ __align__(128) float g_t [B_ * N_ * DIM_];    // [B][128][512]  (I+A)h
__device__ __align__(128) float g_wT[NIT_ * DIM_ * DIM_ + DIM_ * NA_]; // wT (+embed)

// ---------------------------------------------------------------------------
// helpers
// ---------------------------------------------------------------------------
__device__ __forceinline__ void split2u(float a0, float a1, uint32_t& hi, uint32_t& lo) {
    __half2 h = __floats2half2_rn(a0, a1);
    float2  f = __half22float2(h);
    __half2 l = __floats2half2_rn(a0 - f.x, a1 - f.y);
    hi = *reinterpret_cast<uint32_t*>(&h);
    lo = *reinterpret_cast<uint32_t*>(&l);
}
__device__ __forceinline__ uint32_t smem_u32(const void* p) {
    uint32_t a;
    asm("{ .reg .u64 t; cvta.to.shared.u64 t, %1; cvt.u32.u64 %0, t; }" : "=r"(a) : "l"(p));
    return a;
}
#define LDSM4(r, addr) \
    asm volatile("ldmatrix.sync.aligned.m8n8.x4.shared.b16 {%0,%1,%2,%3}, [%4];" \
        : "=r"((r)[0]), "=r"((r)[1]), "=r"((r)[2]), "=r"((r)[3]) : "r"(addr))

__device__ __forceinline__ void mma16816(float* c, const uint32_t* a,
                                         uint32_t b0, uint32_t b1) {
    asm volatile(
        "mma.sync.aligned.m16n8k16.row.col.f32.f16.f16.f32 "
        "{%0,%1,%2,%3}, {%4,%5,%6,%7}, {%8,%9}, {%0,%1,%2,%3};"
        : "+f"(c[0]), "+f"(c[1]), "+f"(c[2]), "+f"(c[3])
        : "r"(a[0]), "r"(a[1]), "r"(a[2]), "r"(a[3]), "r"(b0), "r"(b1));
}

// swizzled byte offset inside one [128 row][64B] tile:
//   16B slot kh (0..3) of row r placed at kh ^ ((r>>1)&3)
__device__ __forceinline__ uint32_t swz(int r, int kh) {
    return (uint32_t)(r * 64) + (uint32_t)((kh ^ ((r >> 1) & 3)) << 4);
}

// ---------------------------------------------------------------------------
// Prep kernels
// ---------------------------------------------------------------------------
__global__ void asum_kernel(const float* __restrict__ adj, float* __restrict__ asumI) {
    int g = blockIdx.x * 256 + threadIdx.x;            // over B*N*N/4, exact
    const float4* p = (const float4*)adj + (long long)g * 5;
    float4 f0 = p[0], f1 = p[1], f2 = p[2], f3 = p[3], f4 = p[4];
    float4 o;
    o.x = (f0.y + f0.z) + (f0.w + f1.x);
    o.y = (f1.z + f1.w) + (f2.x + f2.y);
    o.z = (f2.w + f3.x) + (f3.y + f3.z);
    o.w = (f4.x + f4.y) + (f4.z + f4.w);
    int i = g * 4;
    #pragma unroll
    for (int j = 0; j < 4; j++) {
        int nm = (i + j) & (N_ * N_ - 1);
        if ((nm >> 7) == (nm & 127)) (&o.x)[j] += 1.0f;   // fold residual (+I)
    }
    ((float4*)asumI)[g] = o;
}

__global__ void wtrans_kernel(const float* __restrict__ W_layers,
                              const float* __restrict__ W_embed,
                              float* __restrict__ wT) {
    int i = blockIdx.x * 256 + threadIdx.x;            // exact grid
    const int LSZ = DIM_ * DIM_;
    if (i < NIT_ * LSZ) {
        int l = i / LSZ, j = i % LSZ;
        int c = j / DIM_, r = j % DIM_;
        wT[i] = W_layers[l * LSZ + r * DIM_ + c];
    } else {
        int j = i - NIT_ * LSZ;
        int c = j / NA_, r = j % NA_;
        wT[i] = W_embed[r * DIM_ + c];
    }
}

// ---------------------------------------------------------------------------
// 3xFP16-split tensor GEMM (ldmatrix edition), 512 threads, 16 warps 32x32:
//   D[128,128] tile of A[M,K] @ B[N,K]^T, fp32 K-major inputs.
//   acc = Ah*Bh + Ah*Bl + Al*Bh; B pre-scaled by bScale at split;
//   epilogue v = acc*outScale + bias, optional relu.
// Smem: [2 buf][AH,AL,BH,BL] tiles of [128 rows][64B] (chunk K=32), XOR-16B
//   swizzle -> conflict-free STS.128 and ldmatrix. 1 syncthreads / 32-K chunk.
// ---------------------------------------------------------------------------
#define TILE_BYTES 8192
#define OFF_AH 0
#define OFF_AL 8192
#define OFF_BH 16384
#define OFF_BL 24576
#define BUF_BYTES  32768
#define SMEM_BYTES 65536

__global__ __launch_bounds__(512, 1)
void tgemm(const float* __restrict__ A, long long aBS,
           const float* __restrict__ Bm, long long bBS,
           float* __restrict__ D, long long dBS,
           const float* __restrict__ bias,
           int K, int Nglob, int ntiles, int relu,
           float bScale, float outScale)
{
    extern __shared__ char smem[];
    const uint32_t sb = smem_u32(smem);

    const int tid  = threadIdx.x;
    const int lane = tid & 31;
    const int warp = tid >> 5;             // 0..15
    const int mtb  = blockIdx.x / ntiles;
    const int ntb  = blockIdx.x % ntiles;
    const int wm   = (warp >> 2) * 32;
    const int wn   = (warp & 3) * 32;

    const float* Ap = A  + aBS * blockIdx.y + (long long)mtb * 128 * K;
    const float* Bp = Bm + bBS * blockIdx.y + (long long)ntb * 128 * K;

    // ---- STS mapping: row = tid>>2, 16B k-slot = tid&3 (chunk = 32 floats) ----
    const int sr = tid >> 2;
    const int sk = tid & 3;
    const uint32_t stOff = swz(sr, sk);
    char* stAH = smem + OFF_AH + stOff;
    char* stAL = smem + OFF_AL + stOff;
    char* stBH = smem + OFF_BH + stOff;
    char* stBL = smem + OFF_BL + stOff;
    const float* ag = Ap + (long long)sr * K + sk * 8;
    const float* bg = Bp + (long long)sr * K + sk * 8;

    // ---- ldmatrix address precompute ----
    // A groups: g0 m0-7/k0-7, g1 m8-15/k0-7, g2 m0-7/k8-15, g3 m8-15/k8-15
    const int lane8 = lane & 7;
    const int rA0   = ((lane >> 3) & 1) * 8 + lane8;   // + wm + mt*16
    const int khA   = lane >> 4;                        // 0/1
    // B groups: g0 n0-7/k0-7, g1 n0-7/k8-15, g2 n8-15/k0-7, g3 n8-15/k8-15
    const int rB0   = ((lane >> 4) & 1) * 8 + lane8;   // + wn + nt*16
    const int khB   = (lane >> 3) & 1;

    uint32_t aAddr[2][2], bAddr[2][2];                  // [mt|nt][kslice]
    #pragma unroll
    for (int mt = 0; mt < 2; mt++) {
        const int r = wm + mt * 16 + rA0;
        #pragma unroll
        for (int s = 0; s < 2; s++) aAddr[mt][s] = swz(r, s * 2 + khA);
    }
    #pragma unroll
    for (int nt = 0; nt < 2; nt++) {
        const int r = wn + nt * 16 + rB0;
        #pragma unroll
        for (int s = 0; s < 2; s++) bAddr[nt][s] = swz(r, s * 2 + khB);
    }

    float acc[2][4][4];
    #pragma unroll
    for (int i = 0; i < 2; i++)
        #pragma unroll
        for (int j = 0; j < 4; j++)
            #pragma unroll
            for (int q = 0; q < 4; q++) acc[i][j][q] = 0.0f;

    const int C = K >> 5;                  // 32-K chunks
    int buf = 0;

    float4 aR0 = *(const float4*)(ag);
    float4 aR1 = *(const float4*)(ag + 4);
    float4 bR0 = *(const float4*)(bg);
    float4 bR1 = *(const float4*)(bg + 4);

    for (int c = 0; c < C; c++) {
        // ---- split + STS.128 chunk c ----
        {
            const uint32_t bo = (uint32_t)buf * BUF_BYTES;
            uint32_t h0, h1, h2, h3, l0, l1, l2, l3;
            split2u(aR0.x, aR0.y, h0, l0);
            split2u(aR0.z, aR0.w, h1, l1);
            split2u(aR1.x, aR1.y, h2, l2);
            split2u(aR1.z, aR1.w, h3, l3);
            *(uint4*)(stAH + bo) = make_uint4(h0, h1, h2, h3);
            *(uint4*)(stAL + bo) = make_uint4(l0, l1, l2, l3);
            split2u(bR0.x * bScale, bR0.y * bScale, h0, l0);
            split2u(bR0.z * bScale, bR0.w * bScale, h1, l1);
            split2u(bR1.x * bScale, bR1.y * bScale, h2, l2);
            split2u(bR1.z * bScale, bR1.w * bScale, h3, l3);
            *(uint4*)(stBH + bo) = make_uint4(h0, h1, h2, h3);
            *(uint4*)(stBL + bo) = make_uint4(l0, l1, l2, l3);
        }
        __syncthreads();

        // prefetch chunk c+1 (overlaps with compute)
        if (c + 1 < C) {
            const int g = (c + 1) * 32;
            aR0 = *(const float4*)(ag + g);
            aR1 = *(const float4*)(ag + g + 4);
            bR0 = *(const float4*)(bg + g);
            bR1 = *(const float4*)(bg + g + 4);
        }

        const uint32_t bb = sb + (uint32_t)buf * BUF_BYTES;
        #pragma unroll
        for (int s = 0; s < 2; s++) {      // two k16 slices
            uint32_t ah[2][4], bh[2][4], x[2][4];
            LDSM4(ah[0], bb + OFF_AH + aAddr[0][s]);
            LDSM4(ah[1], bb + OFF_AH + aAddr[1][s]);
            LDSM4(bh[0], bb + OFF_BH + bAddr[0][s]);
            LDSM4(bh[1], bb + OFF_BH + bAddr[1][s]);
            // term 1: Ah * Bh
            #pragma unroll
            for (int mt = 0; mt < 2; mt++)
                #pragma unroll
                for (int nt = 0; nt < 2; nt++) {
                    mma16816(acc[mt][nt * 2],     ah[mt], bh[nt][0], bh[nt][1]);
                    mma16816(acc[mt][nt * 2 + 1], ah[mt], bh[nt][2], bh[nt][3]);
                }
            // term 3: Ah * Bl
            LDSM4(x[0], bb + OFF_BL + bAddr[0][s]);
            LDSM4(x[1], bb + OFF_BL + bAddr[1][s]);
            #pragma unroll
            for (int mt = 0; mt < 2; mt++)
                #pragma unroll
                for (int nt = 0; nt < 2; nt++) {
                    mma16816(acc[mt][nt * 2],     ah[mt], x[nt][0], x[nt][1]);
                    mma16816(acc[mt][nt * 2 + 1], ah[mt], x[nt][2], x[nt][3]);
                }
            // term 2: Al * Bh
            LDSM4(x[0], bb + OFF_AL + aAddr[0][s]);
            LDSM4(x[1], bb + OFF_AL + aAddr[1][s]);
            #pragma unroll
            for (int mt = 0; mt < 2; mt++)
                #pragma unroll
                for (int nt = 0; nt < 2; nt++) {
                    mma16816(acc[mt][nt * 2],     x[mt], bh[nt][0], bh[nt][1]);
                    mma16816(acc[mt][nt * 2 + 1], x[mt], bh[nt][2], bh[nt][3]);
                }
        }
        buf ^= 1;
    }

    // ---- epilogue ----
    // frag map: c0:(r,cc) c1:(r,cc+1) c2:(r+8,cc) c3:(r+8,cc+1)
    //   r = wm + mt*16 + lane/4,  cc = wn + j*8 + 2*(lane&3)
    float* Dp = D + dBS * blockIdx.y + (long long)mtb * 128 * Nglob + ntb * 128;
    #pragma unroll
    for (int mt = 0; mt < 2; mt++) {
        const int rr0 = wm + mt * 16 + (lane >> 2);
        const int rr1 = rr0 + 8;
        const float bv0 = bias ? bias[mtb * 128 + rr0] : 0.0f;
        const float bv1 = bias ? bias[mtb * 128 + rr1] : 0.0f;
        #pragma unroll
        for (int j = 0; j < 4; j++) {
            const int cc = wn + j * 8 + 2 * (lane & 3);
            float v0 = acc[mt][j][0] * outScale + bv0;
            float v1 = acc[mt][j][1] * outScale + bv0;
            float v2 = acc[mt][j][2] * outScale + bv1;
            float v3 = acc[mt][j][3] * outScale + bv1;
            if (relu) {
                v0 = fmaxf(v0, 0.0f); v1 = fmaxf(v1, 0.0f);
                v2 = fmaxf(v2, 0.0f); v3 = fmaxf(v3, 0.0f);
            }
            *(float2*)(Dp + (long long)rr0 * Nglob + cc) = make_float2(v0, v1);
            *(float2*)(Dp + (long long)rr1 * Nglob + cc) = make_float2(v2, v3);
        }
    }
}

// ---------------------------------------------------------------------------
// finalize: graph_repr[b] = mean_n hT[b][d][n];  logit = repr @ W_out + b_out
// out = [ logit(256) | graph_repr(256*512) ]
// ---------------------------------------------------------------------------
__global__ void finalize_kernel(const float* __restrict__ hT,
                                const float* __restrict__ W_out,
                                const float* __restrict__ b_out,
                                float* __restrict__ out)
{
    const int b = blockIdx.x, tid = threadIdx.x;
    const float* base = hT + (long long)b * DIM_ * N_;
    const float4* r0 = (const float4*)(base + (long long)tid * N_);
    const float4* r1 = (const float4*)(base + (long long)(tid + 256) * N_);
    float s0 = 0.0f, s1 = 0.0f;
    #pragma unroll 8
    for (int j = 0; j < 32; j++) {
        float4 a = r0[j]; s0 += (a.x + a.y) + (a.z + a.w);
        float4 c = r1[j]; s1 += (c.x + c.y) + (c.z + c.w);
    }
    const float g0 = s0 * (1.0f / (float)N_);
    const float g1 = s1 * (1.0f / (float)N_);
    out[B_ + b * DIM_ + tid]       = g0;
    out[B_ + b * DIM_ + tid + 256] = g1;

    __shared__ float red[256];
    red[tid] = g0 * W_out[tid] + g1 * W_out[tid + 256];
    __syncthreads();
    for (int s = 128; s > 0; s >>= 1) {
        if (tid < s) red[tid] += red[tid + s];
        __syncthreads();
    }
    if (tid == 0) out[b] = red[0] + b_out[0];
}

// ---------------------------------------------------------------------------
// launch
// ---------------------------------------------------------------------------
extern "C" void kernel_launch(void* const* d_in, const int* in_sizes, int n_in,
                              void* d_out, int out_size)
{
    const float* adj      = (const float*)d_in[0];
    // d_in[1] = hidden (unused by forward)
    const float* node     = (const float*)d_in[2];
    const float* W_embed  = (const float*)d_in[3];
    const float* b_embed  = (const float*)d_in[4];
    const float* W_layers = (const float*)d_in[5];
    const float* b_layers = (const float*)d_in[6];
    const float* W_out    = (const float*)d_in[7];
    const float* b_out    = (const float*)d_in[8];
    float* out = (float*)d_out;

    float *asumI, *hT, *t, *wT;
    cudaGetSymbolAddress((void**)&asumI, g_asumI);
    cudaGetSymbolAddress((void**)&hT,    g_hT);
    cudaGetSymbolAddress((void**)&t,     g_t);
    cudaGetSymbolAddress((void**)&wT,    g_wT);

    cudaFuncSetAttribute(tgemm, cudaFuncAttributeMaxDynamicSharedMemorySize,
                         SMEM_BYTES);

    // prep: folded adjacency (+I), fused weight transposes
    asum_kernel<<<(B_ * N_ * N_ / 4) / 256, 256>>>(adj, asumI);
    wtrans_kernel<<<(NIT_ * DIM_ * DIM_ + DIM_ * NA_) / 256, 256>>>(
        W_layers, W_embed, wT);

    dim3 grid(4, B_);
    const float S  = 1.0f / 64.0f;   // B-operand pre-scale (fp16 range safety)
    const float iS = 64.0f;

    // embed: hT[b][512][128] = WembT @ node[b]^T + b_embed   (K=64)
    tgemm<<<grid, 512, SMEM_BYTES>>>(
        wT + (long long)NIT_ * DIM_ * DIM_, 0LL,
        node, (long long)N_ * NA_,
        hT, (long long)DIM_ * N_,
        b_embed, NA_, N_, /*ntiles=*/1, /*relu=*/0, 1.0f, 1.0f);

    for (int i = 0; i < NIT_; i++) {
        // t[b][128x512] = asumI[b] @ hT[b]^T   (K=128)
        tgemm<<<grid, 512, SMEM_BYTES>>>(
            asumI, (long long)N_ * N_,
            hT, (long long)DIM_ * N_,
            t, (long long)N_ * DIM_,
            nullptr, N_, DIM_, /*ntiles=*/4, /*relu=*/0, S, iS);
        // hT[b][512x128] = relu(WT_i @ t[b]^T + b_i)   (K=512)
        tgemm<<<grid, 512, SMEM_BYTES>>>(
            wT + (long long)i * DIM_ * DIM_, 0LL,
            t, (long long)N_ * DIM_,
            hT, (long long)DIM_ * N_,
            b_layers + i * DIM_, DIM_, N_, /*ntiles=*/1, /*relu=*/1, S, iS);
    }

    finalize_kernel<<<B_, 256>>>(hT, W_out, b_out, out);
}

// round 10
// speedup vs baseline: 1.5455x; 1.2472x over previous
#include <cuda_runtime.h>
#include <cuda_fp16.h>
#include <cstdint>

// Problem constants
#define B_    256
#define N_    128
#define EB_   5
#define NA_   64
#define DIM_  512
#define NIT_  3
#define MROWS (B_ * N_)
#define WSZ   (NIT_ * DIM_ * DIM_ + DIM_ * NA_)

// Scratch (static device globals)
__device__ __align__(128) float  g_hT[B_ * DIM_ * N_];   // [B][512][128] hidden (transposed)
__device__ __align__(128) float  g_t [B_ * N_ * DIM_];   // [B][128][512] (I+A)h
__device__ __align__(128) __half g_wh[WSZ];              // wT (+embed), pre-split hi
__device__ __align__(128) __half g_wl[WSZ];              //               pre-split lo
__device__ __align__(128) __half g_ah[B_ * N_ * N_];     // Σedges + I, hi
__device__ __align__(128) __half g_al[B_ * N_ * N_];     //             lo

// ---------------------------------------------------------------------------
// helpers
// ---------------------------------------------------------------------------
__device__ __forceinline__ void split2u(float a0, float a1, uint32_t& hi, uint32_t& lo) {
    __half2 h = __floats2half2_rn(a0, a1);
    float2  f = __half22float2(h);
    __half2 l = __floats2half2_rn(a0 - f.x, a1 - f.y);
    hi = *reinterpret_cast<uint32_t*>(&h);
    lo = *reinterpret_cast<uint32_t*>(&l);
}
__device__ __forceinline__ uint32_t smem_u32(const void* p) {
    uint32_t a;
    asm("{ .reg .u64 t; cvta.to.shared.u64 t, %1; cvt.u32.u64 %0, t; }" : "=r"(a) : "l"(p));
    return a;
}
__device__ __forceinline__ void cpasync16(uint32_t s, const void* g) {
    asm volatile("cp.async.cg.shared.global [%0], [%1], 16;" :: "r"(s), "l"(g));
}
#define CP_COMMIT() asm volatile("cp.async.commit_group;" ::: "memory")
#define CP_WAIT(n)  asm volatile("cp.async.wait_group %0;" :: "n"(n) : "memory")

#define LDSM4(r, addr) \
    asm volatile("ldmatrix.sync.aligned.m8n8.x4.shared.b16 {%0,%1,%2,%3}, [%4];" \
        : "=r"((r)[0]), "=r"((r)[1]), "=r"((r)[2]), "=r"((r)[3]) : "r"(addr))

__device__ __forceinline__ void mma16816(float* c, const uint32_t* a,
                                         uint32_t b0, uint32_t b1) {
    asm volatile(
        "mma.sync.aligned.m16n8k16.row.col.f32.f16.f16.f32 "
        "{%0,%1,%2,%3}, {%4,%5,%6,%7}, {%8,%9}, {%0,%1,%2,%3};"
        : "+f"(c[0]), "+f"(c[1]), "+f"(c[2]), "+f"(c[3])
        : "r"(a[0]), "r"(a[1]), "r"(a[2]), "r"(a[3]), "r"(b0), "r"(b1));
}

// swizzled byte offset inside one [128 row][64B] tile
__device__ __forceinline__ uint32_t swz(int r, int kh) {
    return (uint32_t)(r * 64) + (uint32_t)((kh ^ ((r >> 1) & 3)) << 4);
}

// ---------------------------------------------------------------------------
// Prep kernels
// ---------------------------------------------------------------------------
// asum + I, split to half hi/lo (4 outputs per thread, float4 loads)
__global__ void asum_split_kernel(const float* __restrict__ adj,
                                  __half* __restrict__ ah, __half* __restrict__ al) {
    int g = blockIdx.x * 256 + threadIdx.x;            // over B*N*N/4, exact
    const float4* p = (const float4*)adj + (long long)g * 5;
    float4 f0 = p[0], f1 = p[1], f2 = p[2], f3 = p[3], f4 = p[4];
    float4 o;
    o.x = (f0.y + f0.z) + (f0.w + f1.x);
    o.y = (f1.z + f1.w) + (f2.x + f2.y);
    o.z = (f2.w + f3.x) + (f3.y + f3.z);
    o.w = (f4.x + f4.y) + (f4.z + f4.w);
    int i = g * 4;
    #pragma unroll
    for (int j = 0; j < 4; j++) {
        int nm = (i + j) & (N_ * N_ - 1);
        if ((nm >> 7) == (nm & 127)) (&o.x)[j] += 1.0f;   // fold residual (+I)
    }
    uint32_t h0, l0, h1, l1;
    split2u(o.x, o.y, h0, l0);
    split2u(o.z, o.w, h1, l1);
    ((uint2*)ah)[g] = make_uint2(h0, h1);
    ((uint2*)al)[g] = make_uint2(l0, l1);
}

// fused transpose + split of all weights (layers then embed), K-major
__global__ void wsplit_kernel(const float* __restrict__ W_layers,
                              const float* __restrict__ W_embed,
                              __half* __restrict__ wh, __half* __restrict__ wl) {
    int i = blockIdx.x * 256 + threadIdx.x;            // exact grid
    const int LSZ = DIM_ * DIM_;
    float v;
    if (i < NIT_ * LSZ) {
        int l = i / LSZ, j = i % LSZ;
        int c = j / DIM_, r = j % DIM_;
        v = W_layers[l * LSZ + r * DIM_ + c];
    } else {
        int j = i - NIT_ * LSZ;
        int c = j / NA_, r = j % NA_;
        v = W_embed[r * DIM_ + c];
    }
    __half h = __float2half_rn(v);
    wh[i] = h;
    wl[i] = __float2half_rn(v - __half2float(h));
}

// ---------------------------------------------------------------------------
// 3xFP16-split tensor GEMM:  D[128,128] tile of A[M,K] @ B[N,K]^T
//   A pre-split half hi/lo in global (cp.async -> smem, zero reg cost);
//   B fp32 in global, split in-kernel (reg prefetch + STS.128).
//   acc = Ah*Bh + Al*Bh + Ah*Bl;  v = acc*outScale + bias; optional relu.
// 256 threads, 8 warps (4m x 2n) of 32x64 warp tiles; 2 CTAs/SM.
// Smem: [2 buf][AH,AL,BH,BL] of [128 rows][64B] (K-chunk 32), XOR-16B swizzle.
// ---------------------------------------------------------------------------
#define OFF_AH 0
#define OFF_AL 8192
#define OFF_BH 16384
#define OFF_BL 24576
#define BUF_BYTES  32768
#define SMEM_BYTES 65536

__global__ __launch_bounds__(256, 2)
void tgemm(const __half* __restrict__ Ah, const __half* __restrict__ Al, long long aBS,
           const float* __restrict__ Bm, long long bBS,
           float* __restrict__ D, long long dBS,
           const float* __restrict__ bias,
           int K, int Nglob, int ntiles, int relu,
           float bScale, float outScale)
{
    extern __shared__ char smem[];
    const uint32_t sb = smem_u32(smem);

    const int tid  = threadIdx.x;
    const int lane = tid & 31;
    const int warp = tid >> 5;             // 0..7
    const int mtb  = blockIdx.x / ntiles;
    const int ntb  = blockIdx.x % ntiles;
    const int wm   = (warp >> 1) * 32;     // 0,32,64,96
    const int wn   = (warp & 1) * 64;      // 0,64

    const __half* Aph = Ah + aBS * blockIdx.y + (long long)mtb * 128 * K;
    const __half* Apl = Al + aBS * blockIdx.y + (long long)mtb * 128 * K;
    const float*  Bp  = Bm + bBS * blockIdx.y + (long long)ntb * 128 * K;

    // ---- loader mapping: rows lr and lr+64, 16B slot sk ----
    const int lr = tid >> 2;               // 0..63
    const int sk = tid & 3;
    const uint32_t so0 = swz(lr, sk);
    const uint32_t so1 = swz(lr + 64, sk);
    const long long go0 = (long long)lr * K + sk * 8;
    const long long go1 = (long long)(lr + 64) * K + sk * 8;

    // ---- ldmatrix address precompute ----
    const int lane8 = lane & 7;
    const int rA0   = ((lane >> 3) & 1) * 8 + lane8;
    const int khA   = lane >> 4;
    const int rB0   = ((lane >> 4) & 1) * 8 + lane8;
    const int khB   = (lane >> 3) & 1;

    uint32_t aAddr[2][2], bAddr[4][2];     // [mt|nt][kslice]
    #pragma unroll
    for (int mt = 0; mt < 2; mt++) {
        const int r = wm + mt * 16 + rA0;
        #pragma unroll
        for (int s = 0; s < 2; s++) aAddr[mt][s] = swz(r, s * 2 + khA);
    }
    #pragma unroll
    for (int nt = 0; nt < 4; nt++) {
        const int r = wn + nt * 16 + rB0;
        #pragma unroll
        for (int s = 0; s < 2; s++) bAddr[nt][s] = swz(r, s * 2 + khB);
    }

    float acc[2][8][4];
    #pragma unroll
    for (int i = 0; i < 2; i++)
        #pragma unroll
        for (int j = 0; j < 8; j++)
            #pragma unroll
            for (int q = 0; q < 4; q++) acc[i][j][q] = 0.0f;

    const int C = K >> 5;                  // 32-K chunks
    int buf = 0;

    // ---- prologue: A chunk 0 via cp.async; B chunk 0 into regs ----
    {
        const uint32_t bo = sb;
        cpasync16(bo + OFF_AH + so0, Aph + go0);
        cpasync16(bo + OFF_AH + so1, Aph + go1);
        cpasync16(bo + OFF_AL + so0, Apl + go0);
        cpasync16(bo + OFF_AL + so1, Apl + go1);
        CP_COMMIT();
    }
    float4 b00 = *(const float4*)(Bp + go0);
    float4 b01 = *(const float4*)(Bp + go0 + 4);
    float4 b10 = *(const float4*)(Bp + go1);
    float4 b11 = *(const float4*)(Bp + go1 + 4);

    for (int c = 0; c < C; c++) {
        // ---- split + STS.128 of B chunk c ----
        {
            const uint32_t bo = sb + (uint32_t)buf * BUF_BYTES;
            uint32_t h0, h1, h2, h3, l0, l1, l2, l3;
            split2u(b00.x * bScale, b00.y * bScale, h0, l0);
            split2u(b00.z * bScale, b00.w * bScale, h1, l1);
            split2u(b01.x * bScale, b01.y * bScale, h2, l2);
            split2u(b01.z * bScale, b01.w * bScale, h3, l3);
            *(uint4*)(smem + (bo - sb) + OFF_BH + so0) = make_uint4(h0, h1, h2, h3);
            *(uint4*)(smem + (bo - sb) + OFF_BL + so0) = make_uint4(l0, l1, l2, l3);
            split2u(b10.x * bScale, b10.y * bScale, h0, l0);
            split2u(b10.z * bScale, b10.w * bScale, h1, l1);
            split2u(b11.x * bScale, b11.y * bScale, h2, l2);
            split2u(b11.z * bScale, b11.w * bScale, h3, l3);
            *(uint4*)(smem + (bo - sb) + OFF_BH + so1) = make_uint4(h0, h1, h2, h3);
            *(uint4*)(smem + (bo - sb) + OFF_BL + so1) = make_uint4(l0, l1, l2, l3);
        }
        // issue A chunk c+1, then wait for A chunk c
        if (c + 1 < C) {
            const uint32_t bo = sb + (uint32_t)(buf ^ 1) * BUF_BYTES;
            const int g = (c + 1) * 32;
            cpasync16(bo + OFF_AH + so0, Aph + go0 + g);
            cpasync16(bo + OFF_AH + so1, Aph + go1 + g);
            cpasync16(bo + OFF_AL + so0, Apl + go0 + g);
            cpasync16(bo + OFF_AL + so1, Apl + go1 + g);
            CP_COMMIT();
            CP_WAIT(1);
        } else {
            CP_WAIT(0);
        }
        __syncthreads();

        // prefetch B chunk c+1 into regs (overlaps compute)
        if (c + 1 < C) {
            const int g = (c + 1) * 32;
            b00 = *(const float4*)(Bp + go0 + g);
            b01 = *(const float4*)(Bp + go0 + g + 4);
            b10 = *(const float4*)(Bp + go1 + g);
            b11 = *(const float4*)(Bp + go1 + g + 4);
        }

        const uint32_t bb = sb + (uint32_t)buf * BUF_BYTES;
        #pragma unroll
        for (int s = 0; s < 2; s++) {      // two k16 slices
            uint32_t ahf[2][4], bhf[4][4], alf[2][4];
            LDSM4(ahf[0], bb + OFF_AH + aAddr[0][s]);
            LDSM4(ahf[1], bb + OFF_AH + aAddr[1][s]);
            #pragma unroll
            for (int nt = 0; nt < 4; nt++) LDSM4(bhf[nt], bb + OFF_BH + bAddr[nt][s]);
            // term 1: Ah * Bh
            #pragma unroll
            for (int mt = 0; mt < 2; mt++)
                #pragma unroll
                for (int nt = 0; nt < 4; nt++) {
                    mma16816(acc[mt][nt * 2],     ahf[mt], bhf[nt][0], bhf[nt][1]);
                    mma16816(acc[mt][nt * 2 + 1], ahf[mt], bhf[nt][2], bhf[nt][3]);
                }
            // term 2: Al * Bh
            LDSM4(alf[0], bb + OFF_AL + aAddr[0][s]);
            LDSM4(alf[1], bb + OFF_AL + aAddr[1][s]);
            #pragma unroll
            for (int mt = 0; mt < 2; mt++)
                #pragma unroll
                for (int nt = 0; nt < 4; nt++) {
                    mma16816(acc[mt][nt * 2],     alf[mt], bhf[nt][0], bhf[nt][1]);
                    mma16816(acc[mt][nt * 2 + 1], alf[mt], bhf[nt][2], bhf[nt][3]);
                }
            // term 3: Ah * Bl  (Bl overwrites Bh regs)
            #pragma unroll
            for (int nt = 0; nt < 4; nt++) LDSM4(bhf[nt], bb + OFF_BL + bAddr[nt][s]);
            #pragma unroll
            for (int mt = 0; mt < 2; mt++)
                #pragma unroll
                for (int nt = 0; nt < 4; nt++) {
                    mma16816(acc[mt][nt * 2],     ahf[mt], bhf[nt][0], bhf[nt][1]);
                    mma16816(acc[mt][nt * 2 + 1], ahf[mt], bhf[nt][2], bhf[nt][3]);
                }
        }
        buf ^= 1;
    }

    // ---- epilogue ----
    float* Dp = D + dBS * blockIdx.y + (long long)mtb * 128 * Nglob + ntb * 128;
    #pragma unroll
    for (int mt = 0; mt < 2; mt++) {
        const int rr0 = wm + mt * 16 + (lane >> 2);
        const int rr1 = rr0 + 8;
        const float bv0 = bias ? bias[mtb * 128 + rr0] : 0.0f;
        const float bv1 = bias ? bias[mtb * 128 + rr1] : 0.0f;
        #pragma unroll
        for (int j = 0; j < 8; j++) {
            const int cc = wn + j * 8 + 2 * (lane & 3);
            float v0 = acc[mt][j][0] * outScale + bv0;
            float v1 = acc[mt][j][1] * outScale + bv0;
            float v2 = acc[mt][j][2] * outScale + bv1;
            float v3 = acc[mt][j][3] * outScale + bv1;
            if (relu) {
                v0 = fmaxf(v0, 0.0f); v1 = fmaxf(v1, 0.0f);
                v2 = fmaxf(v2, 0.0f); v3 = fmaxf(v3, 0.0f);
            }
            *(float2*)(Dp + (long long)rr0 * Nglob + cc) = make_float2(v0, v1);
            *(float2*)(Dp + (long long)rr1 * Nglob + cc) = make_float2(v2, v3);
        }
    }
}

// ---------------------------------------------------------------------------
// finalize: graph_repr[b] = mean_n hT[b][d][n];  logit = repr @ W_out + b_out
// out = [ logit(256) | graph_repr(256*512) ]
// ---------------------------------------------------------------------------
__global__ void finalize_kernel(const float* __restrict__ hT,
                                const float* __restrict__ W_out,
                                const float* __restrict__ b_out,
                                float* __restrict__ out)
{
    const int b = blockIdx.x, tid = threadIdx.x;
    const float* base = hT + (long long)b * DIM_ * N_;
    const float4* r0 = (const float4*)(base + (long long)tid * N_);
    const float4* r1 = (const float4*)(base + (long long)(tid + 256) * N_);
    float s0 = 0.0f, s1 = 0.0f;
    #pragma unroll 8
    for (int j = 0; j < 32; j++) {
        float4 a = r0[j]; s0 += (a.x + a.y) + (a.z + a.w);
        float4 c = r1[j]; s1 += (c.x + c.y) + (c.z + c.w);
    }
    const float g0 = s0 * (1.0f / (float)N_);
    const float g1 = s1 * (1.0f / (float)N_);
    out[B_ + b * DIM_ + tid]       = g0;
    out[B_ + b * DIM_ + tid + 256] = g1;

    __shared__ float red[256];
    red[tid] = g0 * W_out[tid] + g1 * W_out[tid + 256];
    __syncthreads();
    for (int s = 128; s > 0; s >>= 1) {
        if (tid < s) red[tid] += red[tid + s];
        __syncthreads();
    }
    if (tid == 0) out[b] = red[0] + b_out[0];
}

// ---------------------------------------------------------------------------
// launch
// ---------------------------------------------------------------------------
extern "C" void kernel_launch(void* const* d_in, const int* in_sizes, int n_in,
                              void* d_out, int out_size)
{
    const float* adj      = (const float*)d_in[0];
    // d_in[1] = hidden (unused by forward)
    const float* node     = (const float*)d_in[2];
    const float* W_embed  = (const float*)d_in[3];
    const float* b_embed  = (const float*)d_in[4];
    const float* W_layers = (const float*)d_in[5];
    const float* b_layers = (const float*)d_in[6];
    const float* W_out    = (const float*)d_in[7];
    const float* b_out    = (const float*)d_in[8];
    float* out = (float*)d_out;

    float *hT, *t;
    __half *wh, *wl, *ah, *al;
    cudaGetSymbolAddress((void**)&hT, g_hT);
    cudaGetSymbolAddress((void**)&t,  g_t);
    cudaGetSymbolAddress((void**)&wh, g_wh);
    cudaGetSymbolAddress((void**)&wl, g_wl);
    cudaGetSymbolAddress((void**)&ah, g_ah);
    cudaGetSymbolAddress((void**)&al, g_al);

    cudaFuncSetAttribute(tgemm, cudaFuncAttributeMaxDynamicSharedMemorySize,
                         SMEM_BYTES);

    // prep: folded adjacency (+I) split, fused weight transpose+split
    asum_split_kernel<<<(B_ * N_ * N_ / 4) / 256, 256>>>(adj, ah, al);
    wsplit_kernel<<<WSZ / 256, 256>>>(W_layers, W_embed, wh, wl);

    dim3 grid(4, B_);
    const float S  = 1.0f / 64.0f;   // B-operand pre-scale (fp16 range safety)
    const float iS = 64.0f;

    // embed: hT[b][512][128] = WembT @ node[b]^T + b_embed   (K=64)
    tgemm<<<grid, 256, SMEM_BYTES>>>(
        wh + (long long)NIT_ * DIM_ * DIM_, wl + (long long)NIT_ * DIM_ * DIM_, 0LL,
        node, (long long)N_ * NA_,
        hT, (long long)DIM_ * N_,
        b_embed, NA_, N_, /*ntiles=*/1, /*relu=*/0, 1.0f, 1.0f);

    for (int i = 0; i < NIT_; i++) {
        // t[b][128x512] = asumI[b] @ hT[b]^T   (K=128)
        tgemm<<<grid, 256, SMEM_BYTES>>>(
            ah, al, (long long)N_ * N_,
            hT, (long long)DIM_ * N_,
            t, (long long)N_ * DIM_,
            nullptr, N_, DIM_, /*ntiles=*/4, /*relu=*/0, S, iS);
        // hT[b][512x128] = relu(WT_i @ t[b]^T + b_i)   (K=512)
        tgemm<<<grid, 256, SMEM_BYTES>>>(
            wh + (long long)i * DIM_ * DIM_, wl + (long long)i * DIM_ * DIM_, 0LL,
            t, (long long)N_ * DIM_,
            hT, (long long)DIM_ * N_,
            b_layers + i * DIM_, DIM_, N_, /*ntiles=*/1, /*relu=*/1, S, iS);
    }

    finalize_kernel<<<B_, 256>>>(hT, W_out, b_out, out);
}